// round 2
// baseline (speedup 1.0000x reference)
#include <cuda_runtime.h>
#include <math.h>

#define T_TOK 4096
#define H_DIM 2048
#define I_DIM 6144

// ---------------- scratch (static __device__ — no allocations allowed) ----------------
__device__ float g_xq[(size_t)T_TOK * H_DIM];       // quantized activations
__device__ float g_wup[(size_t)I_DIM * H_DIM];      // dequantized weights
__device__ float g_wgate[(size_t)I_DIM * H_DIM];
__device__ float g_wdown[(size_t)H_DIM * I_DIM];
__device__ float g_up[(size_t)T_TOK * I_DIM];       // up_raw -> silu(up_q)
__device__ float g_gate[(size_t)T_TOK * I_DIM];     // gate_raw -> gate_q -> mid
__device__ unsigned g_absmax[8];                    // slots: 0=x 1=up 2=gate 3=act 4=mid

// ---------------- helpers ----------------
__device__ __forceinline__ float qdq_val(float v, float s, float lo, float hi) {
    // IEEE division + rintf (round-half-even) to match jnp exactly
    float q = rintf(v / s);
    q = fminf(fmaxf(q, lo), hi);
    return q * s;
}
__device__ __forceinline__ float get_scale(int slot, float qmax) {
    return fmaxf(__uint_as_float(g_absmax[slot]) / qmax, 1e-12f);
}
__device__ __forceinline__ void warp_atomic_absmax(int slot, float v) {
    #pragma unroll
    for (int o = 16; o; o >>= 1) v = fmaxf(v, __shfl_xor_sync(0xffffffffu, v, o));
    if ((threadIdx.x & 31) == 0) atomicMax(&g_absmax[slot], __float_as_uint(v));
}

// ---------------- kernels ----------------
__global__ void k_zero() { if (threadIdx.x < 8) g_absmax[threadIdx.x] = 0u; }

__global__ void k_absmax4(const float4* __restrict__ x, size_t n4, int slot) {
    size_t i  = (size_t)blockIdx.x * blockDim.x + threadIdx.x;
    size_t st = (size_t)gridDim.x * blockDim.x;
    float m = 0.f;
    for (; i < n4; i += st) {
        float4 v = x[i];
        m = fmaxf(m, fmaxf(fmaxf(fabsf(v.x), fabsf(v.y)), fmaxf(fabsf(v.z), fabsf(v.w))));
    }
    warp_atomic_absmax(slot, m);
}

__global__ void k_qdq4(const float4* __restrict__ in, float4* __restrict__ out,
                       size_t n4, int slot, float qmax, float lo, float hi) {
    float s = get_scale(slot, qmax);
    size_t i  = (size_t)blockIdx.x * blockDim.x + threadIdx.x;
    size_t st = (size_t)gridDim.x * blockDim.x;
    for (; i < n4; i += st) {
        float4 v = in[i];
        v.x = qdq_val(v.x, s, lo, hi);
        v.y = qdq_val(v.y, s, lo, hi);
        v.z = qdq_val(v.z, s, lo, hi);
        v.w = qdq_val(v.w, s, lo, hi);
        out[i] = v;
    }
}

// LPBQ weight dequant: one thread handles one 32-element block (contiguous along K)
__global__ void k_dqw(const float* __restrict__ w, float* __restrict__ o, size_t nblk) {
    size_t i  = (size_t)blockIdx.x * blockDim.x + threadIdx.x;
    size_t st = (size_t)gridDim.x * blockDim.x;
    for (; i < nblk; i += st) {
        const float4* p = (const float4*)(w + i * 32);
        float4 v[8];
        float m = 0.f;
        #pragma unroll
        for (int j = 0; j < 8; j++) {
            v[j] = p[j];
            m = fmaxf(m, fmaxf(fmaxf(fabsf(v[j].x), fabsf(v[j].y)),
                               fmaxf(fabsf(v[j].z), fabsf(v[j].w))));
        }
        float s = fmaxf(m / 7.0f, 1e-12f);
        float4* q = (float4*)(o + i * 32);
        #pragma unroll
        for (int j = 0; j < 8; j++) {
            float4 t = v[j];
            t.x = qdq_val(t.x, s, -8.f, 7.f);
            t.y = qdq_val(t.y, s, -8.f, 7.f);
            t.z = qdq_val(t.z, s, -8.f, 7.f);
            t.w = qdq_val(t.w, s, -8.f, 7.f);
            q[j] = t;
        }
    }
}

// C[M,N] = A[M,K] @ B[N,K]^T, fp32, 128x128x8 tile, 8x8 per thread,
// optional fused |C| amax into g_absmax[slot].
__global__ void __launch_bounds__(256)
k_gemm_nt(const float* __restrict__ A, const float* __restrict__ B,
          float* __restrict__ C, int M, int N, int K, int slot) {
    __shared__ float As[8][128];
    __shared__ float Bs[8][128];
    const int tid  = threadIdx.x;
    const int warp = tid >> 5, lane = tid & 31;
    const int wm = warp >> 2;          // 0..1   (M)
    const int wn = warp & 3;           // 0..3   (N)
    const int lm = lane >> 2;          // 0..7
    const int ln = lane & 3;           // 0..3
    const int row0 = wm * 64 + lm * 8; // within 128 tile
    const int col0 = wn * 32 + ln * 8;
    const int lrow = tid >> 1;
    const int lcol = (tid & 1) << 2;

    const float* Ab = A + (size_t)blockIdx.y * 128 * K + (size_t)lrow * K + lcol;
    const float* Bb = B + (size_t)blockIdx.x * 128 * K + (size_t)lrow * K + lcol;

    float acc[8][8];
    #pragma unroll
    for (int i = 0; i < 8; i++)
        #pragma unroll
        for (int j = 0; j < 8; j++) acc[i][j] = 0.f;

    for (int k0 = 0; k0 < K; k0 += 8) {
        float4 a4 = *(const float4*)(Ab + k0);
        float4 b4 = *(const float4*)(Bb + k0);
        As[lcol + 0][lrow] = a4.x; As[lcol + 1][lrow] = a4.y;
        As[lcol + 2][lrow] = a4.z; As[lcol + 3][lrow] = a4.w;
        Bs[lcol + 0][lrow] = b4.x; Bs[lcol + 1][lrow] = b4.y;
        Bs[lcol + 2][lrow] = b4.z; Bs[lcol + 3][lrow] = b4.w;
        __syncthreads();
        #pragma unroll
        for (int k = 0; k < 8; k++) {
            float a[8], b[8];
            *(float4*)&a[0] = *(const float4*)&As[k][row0];
            *(float4*)&a[4] = *(const float4*)&As[k][row0 + 4];
            *(float4*)&b[0] = *(const float4*)&Bs[k][col0];
            *(float4*)&b[4] = *(const float4*)&Bs[k][col0 + 4];
            #pragma unroll
            for (int i = 0; i < 8; i++)
                #pragma unroll
                for (int j = 0; j < 8; j++)
                    acc[i][j] = fmaf(a[i], b[j], acc[i][j]);
        }
        __syncthreads();
    }

    float lmax = 0.f;
    #pragma unroll
    for (int i = 0; i < 8; i++) {
        float* crow = C + (size_t)(blockIdx.y * 128 + row0 + i) * N
                        + blockIdx.x * 128 + col0;
        float4 v0 = make_float4(acc[i][0], acc[i][1], acc[i][2], acc[i][3]);
        float4 v1 = make_float4(acc[i][4], acc[i][5], acc[i][6], acc[i][7]);
        *(float4*)crow       = v0;
        *(float4*)(crow + 4) = v1;
        #pragma unroll
        for (int j = 0; j < 8; j++) lmax = fmaxf(lmax, fabsf(acc[i][j]));
    }
    if (slot >= 0) warp_atomic_absmax(slot, lmax);
}

// P4: up_q = qdq(up,s1); a = silu(up_q) -> g_up; amax|a| -> slot3; gate_q = qdq(gate,s2) -> g_gate
__global__ void k_p4(size_t n4) {
    float s1 = get_scale(1, 32767.f);
    float s2 = get_scale(2, 32767.f);
    float4* up = (float4*)g_up;
    float4* gt = (float4*)g_gate;
    size_t i  = (size_t)blockIdx.x * blockDim.x + threadIdx.x;
    size_t st = (size_t)gridDim.x * blockDim.x;
    float m = 0.f;
    for (; i < n4; i += st) {
        float4 u = up[i];
        float uq, a;
        uq = qdq_val(u.x, s1, -32768.f, 32767.f); a = uq / (1.f + expf(-uq)); u.x = a; m = fmaxf(m, fabsf(a));
        uq = qdq_val(u.y, s1, -32768.f, 32767.f); a = uq / (1.f + expf(-uq)); u.y = a; m = fmaxf(m, fabsf(a));
        uq = qdq_val(u.z, s1, -32768.f, 32767.f); a = uq / (1.f + expf(-uq)); u.z = a; m = fmaxf(m, fabsf(a));
        uq = qdq_val(u.w, s1, -32768.f, 32767.f); a = uq / (1.f + expf(-uq)); u.w = a; m = fmaxf(m, fabsf(a));
        up[i] = u;
        float4 g = gt[i];
        g.x = qdq_val(g.x, s2, -32768.f, 32767.f);
        g.y = qdq_val(g.y, s2, -32768.f, 32767.f);
        g.z = qdq_val(g.z, s2, -32768.f, 32767.f);
        g.w = qdq_val(g.w, s2, -32768.f, 32767.f);
        gt[i] = g;
    }
    warp_atomic_absmax(3, m);
}

// P5: act = qdq(a,s3); mid = gate_q*act -> g_gate; amax|mid| -> slot4
__global__ void k_p5(size_t n4) {
    float s3 = get_scale(3, 32767.f);
    const float4* up = (const float4*)g_up;
    float4* gt = (float4*)g_gate;
    size_t i  = (size_t)blockIdx.x * blockDim.x + threadIdx.x;
    size_t st = (size_t)gridDim.x * blockDim.x;
    float m = 0.f;
    for (; i < n4; i += st) {
        float4 a = up[i];
        float4 g = gt[i];
        float aq, mv;
        aq = qdq_val(a.x, s3, -32768.f, 32767.f); mv = g.x * aq; g.x = mv; m = fmaxf(m, fabsf(mv));
        aq = qdq_val(a.y, s3, -32768.f, 32767.f); mv = g.y * aq; g.y = mv; m = fmaxf(m, fabsf(mv));
        aq = qdq_val(a.z, s3, -32768.f, 32767.f); mv = g.z * aq; g.z = mv; m = fmaxf(m, fabsf(mv));
        aq = qdq_val(a.w, s3, -32768.f, 32767.f); mv = g.w * aq; g.w = mv; m = fmaxf(m, fabsf(mv));
        gt[i] = g;
    }
    warp_atomic_absmax(4, m);
}

// ---------------- launch ----------------
extern "C" void kernel_launch(void* const* d_in, const int* in_sizes, int n_in,
                              void* d_out, int out_size) {
    const float* x      = (const float*)d_in[0];
    const float* w_gate = (const float*)d_in[1];
    const float* w_up   = (const float*)d_in[2];
    const float* w_down = (const float*)d_in[3];
    float* out = (float*)d_out;

    float *p_xq, *p_wup, *p_wgate, *p_wdown, *p_up, *p_gate;
    cudaGetSymbolAddress((void**)&p_xq,    g_xq);
    cudaGetSymbolAddress((void**)&p_wup,   g_wup);
    cudaGetSymbolAddress((void**)&p_wgate, g_wgate);
    cudaGetSymbolAddress((void**)&p_wdown, g_wdown);
    cudaGetSymbolAddress((void**)&p_up,    g_up);
    cudaGetSymbolAddress((void**)&p_gate,  g_gate);

    const int GS = 1184;  // 8 blocks/SM grid-stride
    const size_t nx4 = (size_t)T_TOK * H_DIM / 4;
    const size_t nti4 = (size_t)T_TOK * I_DIM / 4;
    const size_t nblk_upgate = (size_t)I_DIM * H_DIM / 32;
    const size_t nblk_down   = (size_t)H_DIM * I_DIM / 32;

    k_zero<<<1, 32>>>();
    // x scale + quantize
    k_absmax4<<<GS, 256>>>((const float4*)x, nx4, 0);
    k_qdq4<<<GS, 256>>>((const float4*)x, (float4*)p_xq, nx4, 0, 32767.f, -32768.f, 32767.f);
    // weight dequant (LPBQ int4, block 32)
    k_dqw<<<GS, 256>>>(w_up,   p_wup,   nblk_upgate);
    k_dqw<<<GS, 256>>>(w_gate, p_wgate, nblk_upgate);
    k_dqw<<<GS, 256>>>(w_down, p_wdown, nblk_down);
    // up / gate GEMMs with fused amax
    dim3 g1(I_DIM / 128, T_TOK / 128);
    k_gemm_nt<<<g1, 256>>>(p_xq, p_wup,   p_up,   T_TOK, I_DIM, H_DIM, 1);
    k_gemm_nt<<<g1, 256>>>(p_xq, p_wgate, p_gate, T_TOK, I_DIM, H_DIM, 2);
    // qdq chain
    k_p4<<<GS, 256>>>(nti4);
    k_p5<<<GS, 256>>>(nti4);
    k_qdq4<<<GS, 256>>>((const float4*)p_gate, (float4*)p_gate, nti4, 4, 32767.f, -32768.f, 32767.f);
    // down GEMM -> out
    dim3 g3(H_DIM / 128, T_TOK / 128);
    k_gemm_nt<<<g3, 256>>>(p_gate, p_wdown, out, T_TOK, H_DIM, I_DIM, -1);
}

// round 4
// speedup vs baseline: 1.5815x; 1.5815x over previous
#include <cuda_runtime.h>
#include <cuda_bf16.h>
#include <math.h>
#include <stdint.h>

#define T_TOK 4096
#define H_DIM 2048
#define I_DIM 6144

// ================= device scratch (static — no runtime alloc) =================
__device__ __nv_bfloat16 g_xh[(size_t)T_TOK * H_DIM];
__device__ __nv_bfloat16 g_xl[(size_t)T_TOK * H_DIM];
__device__ __nv_bfloat16 g_uh[(size_t)I_DIM * H_DIM];
__device__ __nv_bfloat16 g_ul[(size_t)I_DIM * H_DIM];
__device__ __nv_bfloat16 g_gh[(size_t)I_DIM * H_DIM];
__device__ __nv_bfloat16 g_gl[(size_t)I_DIM * H_DIM];
__device__ __nv_bfloat16 g_dh[(size_t)H_DIM * I_DIM];
__device__ __nv_bfloat16 g_dl[(size_t)H_DIM * I_DIM];
__device__ __nv_bfloat16 g_mh[(size_t)T_TOK * I_DIM];
__device__ __nv_bfloat16 g_ml[(size_t)T_TOK * I_DIM];
__device__ float g_up[(size_t)T_TOK * I_DIM];
__device__ float g_gate[(size_t)T_TOK * I_DIM];
__device__ unsigned g_absmax[8]; // 0=x 1=up 2=gate 3=act 4=mid

// ================= helpers =================
__device__ __forceinline__ uint32_t smem_u32(const void* p) {
    uint32_t a;
    asm("{ .reg .u64 t; cvta.to.shared.u64 t, %1; cvt.u32.u64 %0, t; }" : "=r"(a) : "l"(p));
    return a;
}
__device__ __forceinline__ void cp16(uint32_t dst, const void* src) {
    asm volatile("cp.async.cg.shared.global [%0], [%1], 16;" :: "r"(dst), "l"(src));
}
#define CP_COMMIT() asm volatile("cp.async.commit_group;" ::: "memory")

#define LDSM4(r, addr) \
    asm volatile("ldmatrix.sync.aligned.m8n8.x4.shared.b16 {%0,%1,%2,%3}, [%4];" \
        : "=r"((r)[0]), "=r"((r)[1]), "=r"((r)[2]), "=r"((r)[3]) : "r"(addr))

#define MMA_BF16(c, a, b0, b1) \
    asm volatile("mma.sync.aligned.m16n8k16.row.col.f32.bf16.bf16.f32 " \
        "{%0,%1,%2,%3}, {%4,%5,%6,%7}, {%8,%9}, {%0,%1,%2,%3};" \
        : "+f"((c)[0]), "+f"((c)[1]), "+f"((c)[2]), "+f"((c)[3]) \
        : "r"((a)[0]), "r"((a)[1]), "r"((a)[2]), "r"((a)[3]), "r"(b0), "r"(b1))

__device__ __forceinline__ float qdq_val(float v, float s, float lo, float hi) {
    float q = rintf(v / s);
    return fminf(fmaxf(q, lo), hi) * s;
}
__device__ __forceinline__ float get_scale(int slot, float qmax) {
    return fmaxf(__uint_as_float(g_absmax[slot]) / qmax, 1e-12f);
}
__device__ __forceinline__ void warp_atomic_absmax(int slot, float v) {
    #pragma unroll
    for (int o = 16; o; o >>= 1) v = fmaxf(v, __shfl_xor_sync(0xffffffffu, v, o));
    if ((threadIdx.x & 31) == 0) atomicMax(&g_absmax[slot], __float_as_uint(v));
}

// ================= elementwise kernels =================
__global__ void k_zero() { if (threadIdx.x < 8) g_absmax[threadIdx.x] = 0u; }

__global__ void k_absmax4(const float4* __restrict__ x, size_t n4, int slot) {
    size_t i = (size_t)blockIdx.x * blockDim.x + threadIdx.x;
    size_t st = (size_t)gridDim.x * blockDim.x;
    float m = 0.f;
    for (; i < n4; i += st) {
        float4 v = x[i];
        m = fmaxf(m, fmaxf(fmaxf(fabsf(v.x), fabsf(v.y)), fmaxf(fabsf(v.z), fabsf(v.w))));
    }
    warp_atomic_absmax(slot, m);
}

// quantize fp32 -> exact bf16 hi/lo split of the int16 code (hi=256*round(q/256), lo=q-hi)
__global__ void k_split(const float4* __restrict__ in, __nv_bfloat16* __restrict__ oh,
                        __nv_bfloat16* __restrict__ ol, size_t n4, int slot) {
    float s = get_scale(slot, 32767.f);
    size_t i = (size_t)blockIdx.x * blockDim.x + threadIdx.x;
    size_t st = (size_t)gridDim.x * blockDim.x;
    for (; i < n4; i += st) {
        float4 v = in[i];
        float qs[4] = {rintf(v.x / s), rintf(v.y / s), rintf(v.z / s), rintf(v.w / s)};
        __nv_bfloat16 h[4], l[4];
        #pragma unroll
        for (int j = 0; j < 4; j++) {
            float q = fminf(fmaxf(qs[j], -32768.f), 32767.f);
            float qh = rintf(q * 0.00390625f) * 256.f;   // exact
            h[j] = __float2bfloat16_rn(qh);              // exact (multiple of 256, |.|<=32768)
            l[j] = __float2bfloat16_rn(q - qh);          // exact (|.|<=128 integer)
        }
        __nv_bfloat162* ph = (__nv_bfloat162*)(oh + 4 * i);
        __nv_bfloat162* pl = (__nv_bfloat162*)(ol + 4 * i);
        ph[0] = __nv_bfloat162{h[0], h[1]}; ph[1] = __nv_bfloat162{h[2], h[3]};
        pl[0] = __nv_bfloat162{l[0], l[1]}; pl[1] = __nv_bfloat162{l[2], l[3]};
    }
}

// LPBQ weight dequant + two-level bf16 split (hi = bf16(wq), lo = bf16(wq - hi))
__global__ void k_dqw_split(const float* __restrict__ w, __nv_bfloat16* __restrict__ oh,
                            __nv_bfloat16* __restrict__ ol, size_t nblk) {
    size_t i = (size_t)blockIdx.x * blockDim.x + threadIdx.x;
    size_t st = (size_t)gridDim.x * blockDim.x;
    for (; i < nblk; i += st) {
        const float4* p = (const float4*)(w + i * 32);
        float4 v[8];
        float m = 0.f;
        #pragma unroll
        for (int j = 0; j < 8; j++) {
            v[j] = p[j];
            m = fmaxf(m, fmaxf(fmaxf(fabsf(v[j].x), fabsf(v[j].y)),
                               fmaxf(fabsf(v[j].z), fabsf(v[j].w))));
        }
        float s = fmaxf(m / 7.0f, 1e-12f);
        __nv_bfloat16* qh = oh + i * 32;
        __nv_bfloat16* ql = ol + i * 32;
        #pragma unroll
        for (int j = 0; j < 8; j++) {
            float t[4] = {v[j].x, v[j].y, v[j].z, v[j].w};
            #pragma unroll
            for (int e = 0; e < 4; e++) {
                float wq = qdq_val(t[e], s, -8.f, 7.f);
                __nv_bfloat16 hi = __float2bfloat16_rn(wq);
                float r = wq - __bfloat162float(hi);
                qh[j * 4 + e] = hi;
                ql[j * 4 + e] = __float2bfloat16_rn(r);
            }
        }
    }
}

// P4: up_q=qdq(up,s1); a=silu(up_q)->g_up; amax|a|->3; gate_q=qdq(gate,s2)->g_gate
__global__ void k_p4(size_t n4) {
    float s1 = get_scale(1, 32767.f);
    float s2 = get_scale(2, 32767.f);
    float4* up = (float4*)g_up;
    float4* gt = (float4*)g_gate;
    size_t i = (size_t)blockIdx.x * blockDim.x + threadIdx.x;
    size_t st = (size_t)gridDim.x * blockDim.x;
    float m = 0.f;
    for (; i < n4; i += st) {
        float4 u = up[i];
        float uq, a;
        uq = qdq_val(u.x, s1, -32768.f, 32767.f); a = uq / (1.f + expf(-uq)); u.x = a; m = fmaxf(m, fabsf(a));
        uq = qdq_val(u.y, s1, -32768.f, 32767.f); a = uq / (1.f + expf(-uq)); u.y = a; m = fmaxf(m, fabsf(a));
        uq = qdq_val(u.z, s1, -32768.f, 32767.f); a = uq / (1.f + expf(-uq)); u.z = a; m = fmaxf(m, fabsf(a));
        uq = qdq_val(u.w, s1, -32768.f, 32767.f); a = uq / (1.f + expf(-uq)); u.w = a; m = fmaxf(m, fabsf(a));
        up[i] = u;
        float4 g = gt[i];
        g.x = qdq_val(g.x, s2, -32768.f, 32767.f);
        g.y = qdq_val(g.y, s2, -32768.f, 32767.f);
        g.z = qdq_val(g.z, s2, -32768.f, 32767.f);
        g.w = qdq_val(g.w, s2, -32768.f, 32767.f);
        gt[i] = g;
    }
    warp_atomic_absmax(3, m);
}

// P5: act=qdq(a,s3); mid=gate_q*act -> g_gate; amax|mid|->4
__global__ void k_p5(size_t n4) {
    float s3 = get_scale(3, 32767.f);
    const float4* up = (const float4*)g_up;
    float4* gt = (float4*)g_gate;
    size_t i = (size_t)blockIdx.x * blockDim.x + threadIdx.x;
    size_t st = (size_t)gridDim.x * blockDim.x;
    float m = 0.f;
    for (; i < n4; i += st) {
        float4 a = up[i];
        float4 g = gt[i];
        float aq, mv;
        aq = qdq_val(a.x, s3, -32768.f, 32767.f); mv = g.x * aq; g.x = mv; m = fmaxf(m, fabsf(mv));
        aq = qdq_val(a.y, s3, -32768.f, 32767.f); mv = g.y * aq; g.y = mv; m = fmaxf(m, fabsf(mv));
        aq = qdq_val(a.z, s3, -32768.f, 32767.f); mv = g.z * aq; g.z = mv; m = fmaxf(m, fabsf(mv));
        aq = qdq_val(a.w, s3, -32768.f, 32767.f); mv = g.w * aq; g.w = mv; m = fmaxf(m, fabsf(mv));
        gt[i] = g;
    }
    warp_atomic_absmax(4, m);
}

// ================= mma.sync GEMM =================
// C[M,N] = s_in * (A@B^T), A/B bf16 K-major, 3-term split:
//   phase 0: Ah*Bh, phase 1: Al*Bh, phase 2: Ah*Bl  (all into the same fp32 acc)
// CTA tile 128x256, BK=64, 3-stage cp.async pipeline, 8 warps (warp tile 64x64).
#define BM 128
#define BN 256
#define BK 64
#define STAGES 3
#define A_BYTES (BM * BK * 2)                 // 16384
#define B_BYTES (BN * BK * 2)                 // 32768
#define STAGE_BYTES (A_BYTES + B_BYTES)       // 49152
#define GEMM_SMEM (STAGES * STAGE_BYTES)      // 147456

__device__ __forceinline__ void load_stage(
    int c, int cpk, int m0, int n0, int K, int tid, uint32_t sbase,
    const __nv_bfloat16* __restrict__ Ah, const __nv_bfloat16* __restrict__ Al,
    const __nv_bfloat16* __restrict__ Bh, const __nv_bfloat16* __restrict__ Bl) {
    int p = c / cpk;
    int kk = (c - p * cpk) * BK;
    const __nv_bfloat16* Ap = (p == 1) ? Al : Ah;
    const __nv_bfloat16* Bp = (p == 2) ? Bl : Bh;
    uint32_t st = sbase + (uint32_t)(c % STAGES) * STAGE_BYTES;
    // A: 128 rows x 8 chunks of 16B; thread t -> row t>>1, chunks (t&1)*4 .. +3
    int arow = tid >> 1;
    int ac0 = (tid & 1) * 4;
    const __nv_bfloat16* ag = Ap + (size_t)(m0 + arow) * K + kk + ac0 * 8;
    uint32_t abase = st + (uint32_t)arow * 128;
    #pragma unroll
    for (int j = 0; j < 4; j++) {
        int chunk = ac0 + j;
        cp16(abase + (uint32_t)((chunk ^ (arow & 7)) << 4), ag + j * 8);
    }
    // B: 256 rows x 8 chunks; thread t -> row t, chunks 0..7
    const __nv_bfloat16* bg = Bp + (size_t)(n0 + tid) * K + kk;
    uint32_t bbase = st + A_BYTES + (uint32_t)tid * 128;
    #pragma unroll
    for (int j = 0; j < 8; j++)
        cp16(bbase + (uint32_t)((j ^ (tid & 7)) << 4), bg + j * 8);
    CP_COMMIT();
}

__global__ void __launch_bounds__(256, 1)
k_gemm_mma(const __nv_bfloat16* __restrict__ Ah, const __nv_bfloat16* __restrict__ Al,
           const __nv_bfloat16* __restrict__ Bh, const __nv_bfloat16* __restrict__ Bl,
           float* __restrict__ C, int N, int K, int slot_in, int slot_out) {
    extern __shared__ char smem[];
    const uint32_t sbase = smem_u32(smem);
    const int tid = threadIdx.x;
    const int wid = tid >> 5, lane = tid & 31;
    const int wm = wid >> 2, wn = wid & 3;          // 2 x 4 warp grid
    const int m0 = blockIdx.y * BM, n0 = blockIdx.x * BN;
    const int cpk = K / BK;
    const int total = 3 * cpk;

    float acc[4][8][4];
    #pragma unroll
    for (int i = 0; i < 4; i++)
        #pragma unroll
        for (int j = 0; j < 8; j++)
            #pragma unroll
            for (int e = 0; e < 4; e++) acc[i][j][e] = 0.f;

    // ldmatrix lane address components
    const int a_row_off = (lane & 7) + ((lane & 8) ? 8 : 0);
    const int a_chk = (lane >> 4) & 1;
    const int b_row_off = (lane & 7) + ((lane & 16) ? 8 : 0);
    const int b_chk = (lane >> 3) & 1;

    load_stage(0, cpk, m0, n0, K, tid, sbase, Ah, Al, Bh, Bl);
    load_stage(1, cpk, m0, n0, K, tid, sbase, Ah, Al, Bh, Bl);

    for (int c = 0; c < total; ++c) {
        if (c < total - 1) asm volatile("cp.async.wait_group 1;" ::: "memory");
        else               asm volatile("cp.async.wait_group 0;" ::: "memory");
        __syncthreads();
        if (c + STAGES - 1 < total)
            load_stage(c + STAGES - 1, cpk, m0, n0, K, tid, sbase, Ah, Al, Bh, Bl);

        uint32_t st = sbase + (uint32_t)(c % STAGES) * STAGE_BYTES;
        uint32_t sA = st, sB = st + A_BYTES;
        #pragma unroll
        for (int ks = 0; ks < 4; ks++) {
            uint32_t a[4][4], b[4][4];
            #pragma unroll
            for (int i = 0; i < 4; i++) {
                int row = wm * 64 + i * 16 + a_row_off;
                uint32_t addr = sA + (uint32_t)row * 128
                              + (uint32_t)((((2 * ks + a_chk) ^ (row & 7))) << 4);
                LDSM4(a[i], addr);
            }
            #pragma unroll
            for (int j = 0; j < 4; j++) {
                int row = wn * 64 + j * 16 + b_row_off;
                uint32_t addr = sB + (uint32_t)row * 128
                              + (uint32_t)((((2 * ks + b_chk) ^ (row & 7))) << 4);
                LDSM4(b[j], addr);
            }
            #pragma unroll
            for (int i = 0; i < 4; i++)
                #pragma unroll
                for (int j2 = 0; j2 < 8; j2++)
                    MMA_BF16(acc[i][j2], a[i], b[j2 >> 1][(j2 & 1) * 2],
                             b[j2 >> 1][(j2 & 1) * 2 + 1]);
        }
    }

    // epilogue: scale by s_in, store, fused absmax
    float s = get_scale(slot_in, 32767.f);
    const int g = lane >> 2, q = lane & 3;
    float mx = 0.f;
    #pragma unroll
    for (int i = 0; i < 4; i++) {
        #pragma unroll
        for (int j2 = 0; j2 < 8; j2++) {
            int row = m0 + wm * 64 + i * 16 + g;
            int col = n0 + wn * 64 + j2 * 8 + q * 2;
            float v0 = acc[i][j2][0] * s, v1 = acc[i][j2][1] * s;
            float v2 = acc[i][j2][2] * s, v3 = acc[i][j2][3] * s;
            *(float2*)&C[(size_t)row * N + col] = make_float2(v0, v1);
            *(float2*)&C[(size_t)(row + 8) * N + col] = make_float2(v2, v3);
            mx = fmaxf(mx, fmaxf(fmaxf(fabsf(v0), fabsf(v1)), fmaxf(fabsf(v2), fabsf(v3))));
        }
    }
    if (slot_out >= 0) warp_atomic_absmax(slot_out, mx);
}

// ================= host =================
extern "C" void kernel_launch(void* const* d_in, const int* in_sizes, int n_in,
                              void* d_out, int out_size) {
    const float* x      = (const float*)d_in[0];
    const float* w_gate = (const float*)d_in[1];
    const float* w_up   = (const float*)d_in[2];
    const float* w_down = (const float*)d_in[3];
    float* out = (float*)d_out;

    void *p_xh, *p_xl, *p_uh, *p_ul, *p_gh, *p_gl, *p_dh, *p_dl, *p_mh, *p_ml, *p_up, *p_gate;
    cudaGetSymbolAddress(&p_xh, g_xh);   cudaGetSymbolAddress(&p_xl, g_xl);
    cudaGetSymbolAddress(&p_uh, g_uh);   cudaGetSymbolAddress(&p_ul, g_ul);
    cudaGetSymbolAddress(&p_gh, g_gh);   cudaGetSymbolAddress(&p_gl, g_gl);
    cudaGetSymbolAddress(&p_dh, g_dh);   cudaGetSymbolAddress(&p_dl, g_dl);
    cudaGetSymbolAddress(&p_mh, g_mh);   cudaGetSymbolAddress(&p_ml, g_ml);
    cudaGetSymbolAddress(&p_up, g_up);   cudaGetSymbolAddress(&p_gate, g_gate);

    static bool once = false;
    if (!once) {
        cudaFuncSetAttribute(k_gemm_mma, cudaFuncAttributeMaxDynamicSharedMemorySize, GEMM_SMEM);
        once = true;
    }

    const int GS = 1184;
    const size_t nx4 = (size_t)T_TOK * H_DIM / 4;
    const size_t nti4 = (size_t)T_TOK * I_DIM / 4;
    const size_t nblk_ug = (size_t)I_DIM * H_DIM / 32;
    const size_t nblk_d  = (size_t)H_DIM * I_DIM / 32;

    k_zero<<<1, 32>>>();
    k_absmax4<<<GS, 256>>>((const float4*)x, nx4, 0);
    k_split<<<GS, 256>>>((const float4*)x, (__nv_bfloat16*)p_xh, (__nv_bfloat16*)p_xl, nx4, 0);
    k_dqw_split<<<GS, 256>>>(w_up,   (__nv_bfloat16*)p_uh, (__nv_bfloat16*)p_ul, nblk_ug);
    k_dqw_split<<<GS, 256>>>(w_gate, (__nv_bfloat16*)p_gh, (__nv_bfloat16*)p_gl, nblk_ug);
    k_dqw_split<<<GS, 256>>>(w_down, (__nv_bfloat16*)p_dh, (__nv_bfloat16*)p_dl, nblk_d);

    dim3 g1(I_DIM / BN, T_TOK / BM);   // 24 x 32
    k_gemm_mma<<<g1, 256, GEMM_SMEM>>>((const __nv_bfloat16*)p_xh, (const __nv_bfloat16*)p_xl,
                                       (const __nv_bfloat16*)p_uh, (const __nv_bfloat16*)p_ul,
                                       (float*)p_up, I_DIM, H_DIM, 0, 1);
    k_gemm_mma<<<g1, 256, GEMM_SMEM>>>((const __nv_bfloat16*)p_xh, (const __nv_bfloat16*)p_xl,
                                       (const __nv_bfloat16*)p_gh, (const __nv_bfloat16*)p_gl,
                                       (float*)p_gate, I_DIM, H_DIM, 0, 2);
    k_p4<<<GS, 256>>>(nti4);
    k_p5<<<GS, 256>>>(nti4);
    k_split<<<GS, 256>>>((const float4*)p_gate, (__nv_bfloat16*)p_mh, (__nv_bfloat16*)p_ml, nti4, 4);

    dim3 g3(H_DIM / BN, T_TOK / BM);   // 8 x 32
    k_gemm_mma<<<g3, 256, GEMM_SMEM>>>((const __nv_bfloat16*)p_mh, (const __nv_bfloat16*)p_ml,
                                       (const __nv_bfloat16*)p_dh, (const __nv_bfloat16*)p_dl,
                                       out, H_DIM, I_DIM, 4, -1);
}

// round 5
// speedup vs baseline: 1.6951x; 1.0719x over previous
#include <cuda_runtime.h>
#include <cuda_bf16.h>
#include <math.h>
#include <stdint.h>

#define T_TOK 4096
#define H_DIM 2048
#define I_DIM 6144

// ================= device scratch (static — no runtime alloc) =================
__device__ __nv_bfloat16 g_xh[(size_t)T_TOK * H_DIM];
__device__ __nv_bfloat16 g_xl[(size_t)T_TOK * H_DIM];
__device__ __nv_bfloat16 g_uh[(size_t)I_DIM * H_DIM];
__device__ __nv_bfloat16 g_ul[(size_t)I_DIM * H_DIM];
__device__ __nv_bfloat16 g_gh[(size_t)I_DIM * H_DIM];
__device__ __nv_bfloat16 g_gl[(size_t)I_DIM * H_DIM];
__device__ __nv_bfloat16 g_dh[(size_t)H_DIM * I_DIM];
__device__ __nv_bfloat16 g_dl[(size_t)H_DIM * I_DIM];
__device__ __nv_bfloat16 g_mh[(size_t)T_TOK * I_DIM];
__device__ __nv_bfloat16 g_ml[(size_t)T_TOK * I_DIM];
__device__ float g_up[(size_t)T_TOK * I_DIM];
__device__ float g_gate[(size_t)T_TOK * I_DIM];
__device__ unsigned g_absmax[8]; // 0=x 1=up 2=gate 3=act 4=mid

// ================= helpers =================
__device__ __forceinline__ uint32_t smem_u32(const void* p) {
    uint32_t a;
    asm("{ .reg .u64 t; cvta.to.shared.u64 t, %1; cvt.u32.u64 %0, t; }" : "=r"(a) : "l"(p));
    return a;
}
__device__ __forceinline__ void cp16(uint32_t dst, const void* src) {
    asm volatile("cp.async.cg.shared.global [%0], [%1], 16;" :: "r"(dst), "l"(src));
}
#define CP_COMMIT() asm volatile("cp.async.commit_group;" ::: "memory")

#define LDSM4(r, addr) \
    asm volatile("ldmatrix.sync.aligned.m8n8.x4.shared.b16 {%0,%1,%2,%3}, [%4];" \
        : "=r"((r)[0]), "=r"((r)[1]), "=r"((r)[2]), "=r"((r)[3]) : "r"(addr))

#define MMA_BF16(c, a, b0, b1) \
    asm volatile("mma.sync.aligned.m16n8k16.row.col.f32.bf16.bf16.f32 " \
        "{%0,%1,%2,%3}, {%4,%5,%6,%7}, {%8,%9}, {%0,%1,%2,%3};" \
        : "+f"((c)[0]), "+f"((c)[1]), "+f"((c)[2]), "+f"((c)[3]) \
        : "r"((a)[0]), "r"((a)[1]), "r"((a)[2]), "r"((a)[3]), "r"(b0), "r"(b1))

__device__ __forceinline__ float qdq_val(float v, float s, float lo, float hi) {
    float q = rintf(v / s);
    return fminf(fmaxf(q, lo), hi) * s;
}
__device__ __forceinline__ float get_scale(int slot, float qmax) {
    return fmaxf(__uint_as_float(g_absmax[slot]) / qmax, 1e-12f);
}
__device__ __forceinline__ void warp_atomic_absmax(int slot, float v) {
    #pragma unroll
    for (int o = 16; o; o >>= 1) v = fmaxf(v, __shfl_xor_sync(0xffffffffu, v, o));
    if ((threadIdx.x & 31) == 0) atomicMax(&g_absmax[slot], __float_as_uint(v));
}
__device__ __forceinline__ uint32_t pack_bf2(__nv_bfloat16 a, __nv_bfloat16 b) {
    __nv_bfloat162 t{a, b};
    return *(uint32_t*)&t;
}
// exact split of int16 code q: hi = 256*round(q/256), lo = q - hi; both exact in bf16
__device__ __forceinline__ void split_q(float q, __nv_bfloat16& h, __nv_bfloat16& l) {
    q = fminf(fmaxf(q, -32768.f), 32767.f);
    float qh = rintf(q * 0.00390625f) * 256.f;
    h = __float2bfloat16_rn(qh);
    l = __float2bfloat16_rn(q - qh);
}

// ================= elementwise kernels =================
__global__ void k_zero() { if (threadIdx.x < 8) g_absmax[threadIdx.x] = 0u; }

__global__ void k_absmax4(const float4* __restrict__ x, size_t n4, int slot) {
    size_t i = (size_t)blockIdx.x * blockDim.x + threadIdx.x;
    size_t st = (size_t)gridDim.x * blockDim.x;
    float m = 0.f;
    for (; i < n4; i += st) {
        float4 v = x[i];
        m = fmaxf(m, fmaxf(fmaxf(fabsf(v.x), fabsf(v.y)), fmaxf(fabsf(v.z), fabsf(v.w))));
    }
    warp_atomic_absmax(slot, m);
}

// quantize fp32 -> exact bf16 hi/lo split; 8 elements per thread, 16B stores
__global__ void k_split(const float4* __restrict__ in, uint4* __restrict__ oh,
                        uint4* __restrict__ ol, size_t n8, int slot) {
    float s = get_scale(slot, 32767.f);
    size_t i = (size_t)blockIdx.x * blockDim.x + threadIdx.x;
    size_t st = (size_t)gridDim.x * blockDim.x;
    for (; i < n8; i += st) {
        float4 v0 = in[2 * i], v1 = in[2 * i + 1];
        float f[8] = {v0.x, v0.y, v0.z, v0.w, v1.x, v1.y, v1.z, v1.w};
        __nv_bfloat16 h[8], l[8];
        #pragma unroll
        for (int j = 0; j < 8; j++) split_q(rintf(f[j] / s), h[j], l[j]);
        oh[i] = make_uint4(pack_bf2(h[0], h[1]), pack_bf2(h[2], h[3]),
                           pack_bf2(h[4], h[5]), pack_bf2(h[6], h[7]));
        ol[i] = make_uint4(pack_bf2(l[0], l[1]), pack_bf2(l[2], l[3]),
                           pack_bf2(l[4], l[5]), pack_bf2(l[6], l[7]));
    }
}

// LPBQ weight dequant + two-level bf16 split; vectorized 16B stores
__global__ void k_dqw_split(const float* __restrict__ w, uint4* __restrict__ oh,
                            uint4* __restrict__ ol, size_t nblk) {
    size_t i = (size_t)blockIdx.x * blockDim.x + threadIdx.x;
    size_t st = (size_t)gridDim.x * blockDim.x;
    for (; i < nblk; i += st) {
        const float4* p = (const float4*)(w + i * 32);
        float4 v[8];
        float m = 0.f;
        #pragma unroll
        for (int j = 0; j < 8; j++) {
            v[j] = p[j];
            m = fmaxf(m, fmaxf(fmaxf(fabsf(v[j].x), fabsf(v[j].y)),
                               fmaxf(fabsf(v[j].z), fabsf(v[j].w))));
        }
        float s = fmaxf(m / 7.0f, 1e-12f);
        uint32_t hw[16], lw[16];
        #pragma unroll
        for (int j = 0; j < 8; j++) {
            float t[4] = {v[j].x, v[j].y, v[j].z, v[j].w};
            __nv_bfloat16 hh[4], ll[4];
            #pragma unroll
            for (int e = 0; e < 4; e++) {
                float wq = qdq_val(t[e], s, -8.f, 7.f);
                __nv_bfloat16 hi = __float2bfloat16_rn(wq);
                hh[e] = hi;
                ll[e] = __float2bfloat16_rn(wq - __bfloat162float(hi));
            }
            hw[2 * j]     = pack_bf2(hh[0], hh[1]);
            hw[2 * j + 1] = pack_bf2(hh[2], hh[3]);
            lw[2 * j]     = pack_bf2(ll[0], ll[1]);
            lw[2 * j + 1] = pack_bf2(ll[2], ll[3]);
        }
        uint4* qh = oh + i * 4;
        uint4* ql = ol + i * 4;
        #pragma unroll
        for (int j = 0; j < 4; j++) {
            qh[j] = make_uint4(hw[4 * j], hw[4 * j + 1], hw[4 * j + 2], hw[4 * j + 3]);
            ql[j] = make_uint4(lw[4 * j], lw[4 * j + 1], lw[4 * j + 2], lw[4 * j + 3]);
        }
    }
}

// P4: up_q=qdq(up,s1); a=silu(up_q)->g_up; amax|a|->3; gate_q=qdq(gate,s2)->g_gate
__global__ void k_p4(size_t n4) {
    float s1 = get_scale(1, 32767.f);
    float s2 = get_scale(2, 32767.f);
    float4* up = (float4*)g_up;
    float4* gt = (float4*)g_gate;
    size_t i = (size_t)blockIdx.x * blockDim.x + threadIdx.x;
    size_t st = (size_t)gridDim.x * blockDim.x;
    float m = 0.f;
    for (; i < n4; i += st) {
        float4 u = up[i];
        float uq, a;
        uq = qdq_val(u.x, s1, -32768.f, 32767.f); a = uq / (1.f + expf(-uq)); u.x = a; m = fmaxf(m, fabsf(a));
        uq = qdq_val(u.y, s1, -32768.f, 32767.f); a = uq / (1.f + expf(-uq)); u.y = a; m = fmaxf(m, fabsf(a));
        uq = qdq_val(u.z, s1, -32768.f, 32767.f); a = uq / (1.f + expf(-uq)); u.z = a; m = fmaxf(m, fabsf(a));
        uq = qdq_val(u.w, s1, -32768.f, 32767.f); a = uq / (1.f + expf(-uq)); u.w = a; m = fmaxf(m, fabsf(a));
        up[i] = u;
        float4 g = gt[i];
        g.x = qdq_val(g.x, s2, -32768.f, 32767.f);
        g.y = qdq_val(g.y, s2, -32768.f, 32767.f);
        g.z = qdq_val(g.z, s2, -32768.f, 32767.f);
        g.w = qdq_val(g.w, s2, -32768.f, 32767.f);
        gt[i] = g;
    }
    warp_atomic_absmax(3, m);
}

// P5: act=qdq(a,s3); mid=gate_q*act -> g_gate; amax|mid|->4
__global__ void k_p5(size_t n4) {
    float s3 = get_scale(3, 32767.f);
    const float4* up = (const float4*)g_up;
    float4* gt = (float4*)g_gate;
    size_t i = (size_t)blockIdx.x * blockDim.x + threadIdx.x;
    size_t st = (size_t)gridDim.x * blockDim.x;
    float m = 0.f;
    for (; i < n4; i += st) {
        float4 a = up[i];
        float4 g = gt[i];
        float aq, mv;
        aq = qdq_val(a.x, s3, -32768.f, 32767.f); mv = g.x * aq; g.x = mv; m = fmaxf(m, fabsf(mv));
        aq = qdq_val(a.y, s3, -32768.f, 32767.f); mv = g.y * aq; g.y = mv; m = fmaxf(m, fabsf(mv));
        aq = qdq_val(a.z, s3, -32768.f, 32767.f); mv = g.z * aq; g.z = mv; m = fmaxf(m, fabsf(mv));
        aq = qdq_val(a.w, s3, -32768.f, 32767.f); mv = g.w * aq; g.w = mv; m = fmaxf(m, fabsf(mv));
        gt[i] = g;
    }
    warp_atomic_absmax(4, m);
}

// ================= mma.sync GEMM =================
// C[M,N] = s_in * (A@B^T), 3-term split: Ah*Bh, Al*Bh, Ah*Bl into one fp32 acc.
// CTA tile 128x256, BK=64, 4-stage cp.async pipeline, 8 warps (warp tile 64x64).
#define BM 128
#define BN 256
#define BK 64
#define STAGES 4
#define A_BYTES (BM * BK * 2)                 // 16384
#define B_BYTES (BN * BK * 2)                 // 32768
#define STAGE_BYTES (A_BYTES + B_BYTES)       // 49152
#define GEMM_SMEM (STAGES * STAGE_BYTES)      // 196608

__device__ __forceinline__ void load_stage(
    int c, int cpk, int m0, int n0, int K, int tid, uint32_t sbase,
    const __nv_bfloat16* __restrict__ Ah, const __nv_bfloat16* __restrict__ Al,
    const __nv_bfloat16* __restrict__ Bh, const __nv_bfloat16* __restrict__ Bl) {
    int p = c / cpk;
    int kk = (c - p * cpk) * BK;
    const __nv_bfloat16* Ap = (p == 1) ? Al : Ah;
    const __nv_bfloat16* Bp = (p == 2) ? Bl : Bh;
    uint32_t st = sbase + (uint32_t)(c % STAGES) * STAGE_BYTES;
    int arow = tid >> 1;
    int ac0 = (tid & 1) * 4;
    const __nv_bfloat16* ag = Ap + (size_t)(m0 + arow) * K + kk + ac0 * 8;
    uint32_t abase = st + (uint32_t)arow * 128;
    #pragma unroll
    for (int j = 0; j < 4; j++) {
        int chunk = ac0 + j;
        cp16(abase + (uint32_t)((chunk ^ (arow & 7)) << 4), ag + j * 8);
    }
    const __nv_bfloat16* bg = Bp + (size_t)(n0 + tid) * K + kk;
    uint32_t bbase = st + A_BYTES + (uint32_t)tid * 128;
    #pragma unroll
    for (int j = 0; j < 8; j++)
        cp16(bbase + (uint32_t)((j ^ (tid & 7)) << 4), bg + j * 8);
    CP_COMMIT();
}

__global__ void __launch_bounds__(256, 1)
k_gemm_mma(const __nv_bfloat16* __restrict__ Ah, const __nv_bfloat16* __restrict__ Al,
           const __nv_bfloat16* __restrict__ Bh, const __nv_bfloat16* __restrict__ Bl,
           float* __restrict__ C, int N, int K, int slot_in, int slot_out) {
    extern __shared__ char smem[];
    const uint32_t sbase = smem_u32(smem);
    const int tid = threadIdx.x;
    const int wid = tid >> 5, lane = tid & 31;
    const int wm = wid >> 2, wn = wid & 3;          // 2 x 4 warp grid
    const int m0 = blockIdx.y * BM, n0 = blockIdx.x * BN;
    const int cpk = K / BK;
    const int total = 3 * cpk;

    float acc[4][8][4];
    #pragma unroll
    for (int i = 0; i < 4; i++)
        #pragma unroll
        for (int j = 0; j < 8; j++)
            #pragma unroll
            for (int e = 0; e < 4; e++) acc[i][j][e] = 0.f;

    const int a_row_off = (lane & 7) + ((lane & 8) ? 8 : 0);
    const int a_chk = (lane >> 4) & 1;
    const int b_row_off = (lane & 7) + ((lane & 16) ? 8 : 0);
    const int b_chk = (lane >> 3) & 1;

    load_stage(0, cpk, m0, n0, K, tid, sbase, Ah, Al, Bh, Bl);
    load_stage(1, cpk, m0, n0, K, tid, sbase, Ah, Al, Bh, Bl);
    load_stage(2, cpk, m0, n0, K, tid, sbase, Ah, Al, Bh, Bl);

    for (int c = 0; c < total; ++c) {
        // wait until stage c is resident; allow up to min(2, total-1-c) groups in flight
        if (c + 2 < total)      asm volatile("cp.async.wait_group 2;" ::: "memory");
        else if (c + 1 < total) asm volatile("cp.async.wait_group 1;" ::: "memory");
        else                    asm volatile("cp.async.wait_group 0;" ::: "memory");
        __syncthreads();
        if (c + STAGES - 1 < total)
            load_stage(c + STAGES - 1, cpk, m0, n0, K, tid, sbase, Ah, Al, Bh, Bl);

        uint32_t st = sbase + (uint32_t)(c % STAGES) * STAGE_BYTES;
        uint32_t sA = st, sB = st + A_BYTES;
        #pragma unroll
        for (int ks = 0; ks < 4; ks++) {
            uint32_t a[4][4], b[4][4];
            #pragma unroll
            for (int i = 0; i < 4; i++) {
                int row = wm * 64 + i * 16 + a_row_off;
                uint32_t addr = sA + (uint32_t)row * 128
                              + (uint32_t)((((2 * ks + a_chk) ^ (row & 7))) << 4);
                LDSM4(a[i], addr);
            }
            #pragma unroll
            for (int j = 0; j < 4; j++) {
                int row = wn * 64 + j * 16 + b_row_off;
                uint32_t addr = sB + (uint32_t)row * 128
                              + (uint32_t)((((2 * ks + b_chk) ^ (row & 7))) << 4);
                LDSM4(b[j], addr);
            }
            #pragma unroll
            for (int i = 0; i < 4; i++)
                #pragma unroll
                for (int j2 = 0; j2 < 8; j2++)
                    MMA_BF16(acc[i][j2], a[i], b[j2 >> 1][(j2 & 1) * 2],
                             b[j2 >> 1][(j2 & 1) * 2 + 1]);
        }
    }

    // epilogue: scale by s_in, store, fused absmax
    float s = get_scale(slot_in, 32767.f);
    const int g = lane >> 2, q = lane & 3;
    float mx = 0.f;
    #pragma unroll
    for (int i = 0; i < 4; i++) {
        #pragma unroll
        for (int j2 = 0; j2 < 8; j2++) {
            int row = m0 + wm * 64 + i * 16 + g;
            int col = n0 + wn * 64 + j2 * 8 + q * 2;
            float v0 = acc[i][j2][0] * s, v1 = acc[i][j2][1] * s;
            float v2 = acc[i][j2][2] * s, v3 = acc[i][j2][3] * s;
            *(float2*)&C[(size_t)row * N + col] = make_float2(v0, v1);
            *(float2*)&C[(size_t)(row + 8) * N + col] = make_float2(v2, v3);
            mx = fmaxf(mx, fmaxf(fmaxf(fabsf(v0), fabsf(v1)), fmaxf(fabsf(v2), fabsf(v3))));
        }
    }
    if (slot_out >= 0) warp_atomic_absmax(slot_out, mx);
}

// ================= host =================
extern "C" void kernel_launch(void* const* d_in, const int* in_sizes, int n_in,
                              void* d_out, int out_size) {
    const float* x      = (const float*)d_in[0];
    const float* w_gate = (const float*)d_in[1];
    const float* w_up   = (const float*)d_in[2];
    const float* w_down = (const float*)d_in[3];
    float* out = (float*)d_out;

    void *p_xh, *p_xl, *p_uh, *p_ul, *p_gh, *p_gl, *p_dh, *p_dl, *p_mh, *p_ml, *p_up, *p_gate;
    cudaGetSymbolAddress(&p_xh, g_xh);   cudaGetSymbolAddress(&p_xl, g_xl);
    cudaGetSymbolAddress(&p_uh, g_uh);   cudaGetSymbolAddress(&p_ul, g_ul);
    cudaGetSymbolAddress(&p_gh, g_gh);   cudaGetSymbolAddress(&p_gl, g_gl);
    cudaGetSymbolAddress(&p_dh, g_dh);   cudaGetSymbolAddress(&p_dl, g_dl);
    cudaGetSymbolAddress(&p_mh, g_mh);   cudaGetSymbolAddress(&p_ml, g_ml);
    cudaGetSymbolAddress(&p_up, g_up);   cudaGetSymbolAddress(&p_gate, g_gate);

    static bool once = false;
    if (!once) {
        cudaFuncSetAttribute(k_gemm_mma, cudaFuncAttributeMaxDynamicSharedMemorySize, GEMM_SMEM);
        once = true;
    }

    const int GS = 1184;
    const size_t nx4 = (size_t)T_TOK * H_DIM / 4;
    const size_t nx8 = (size_t)T_TOK * H_DIM / 8;
    const size_t nti4 = (size_t)T_TOK * I_DIM / 4;
    const size_t nti8 = (size_t)T_TOK * I_DIM / 8;
    const size_t nblk_ug = (size_t)I_DIM * H_DIM / 32;
    const size_t nblk_d  = (size_t)H_DIM * I_DIM / 32;

    k_zero<<<1, 32>>>();
    k_absmax4<<<GS, 256>>>((const float4*)x, nx4, 0);
    k_split<<<GS, 256>>>((const float4*)x, (uint4*)p_xh, (uint4*)p_xl, nx8, 0);
    k_dqw_split<<<GS, 256>>>(w_up,   (uint4*)p_uh, (uint4*)p_ul, nblk_ug);
    k_dqw_split<<<GS, 256>>>(w_gate, (uint4*)p_gh, (uint4*)p_gl, nblk_ug);
    k_dqw_split<<<GS, 256>>>(w_down, (uint4*)p_dh, (uint4*)p_dl, nblk_d);

    dim3 g1(I_DIM / BN, T_TOK / BM);   // 24 x 32
    k_gemm_mma<<<g1, 256, GEMM_SMEM>>>((const __nv_bfloat16*)p_xh, (const __nv_bfloat16*)p_xl,
                                       (const __nv_bfloat16*)p_uh, (const __nv_bfloat16*)p_ul,
                                       (float*)p_up, I_DIM, H_DIM, 0, 1);
    k_gemm_mma<<<g1, 256, GEMM_SMEM>>>((const __nv_bfloat16*)p_xh, (const __nv_bfloat16*)p_xl,
                                       (const __nv_bfloat16*)p_gh, (const __nv_bfloat16*)p_gl,
                                       (float*)p_gate, I_DIM, H_DIM, 0, 2);
    k_p4<<<GS, 256>>>(nti4);
    k_p5<<<GS, 256>>>(nti4);
    k_split<<<GS, 256>>>((const float4*)p_gate, (uint4*)p_mh, (uint4*)p_ml, nti8, 4);

    dim3 g3(H_DIM / BN, T_TOK / BM);   // 8 x 32
    k_gemm_mma<<<g3, 256, GEMM_SMEM>>>((const __nv_bfloat16*)p_mh, (const __nv_bfloat16*)p_ml,
                                       (const __nv_bfloat16*)p_dh, (const __nv_bfloat16*)p_dl,
                                       out, H_DIM, I_DIM, 4, -1);
}